// round 2
// baseline (speedup 1.0000x reference)
#include <cuda_runtime.h>

#define B_ 8
#define H_ 64
#define W_ 64
#define C_ 256
#define N_ 512
#define POOL_ 7
#define NPOS (POOL_ * POOL_)            // 49
#define NBOX (B_ * N_)                  // 4096
#define NMETA (NBOX * NPOS)             // 200704

// Precomputed per-(box,pos) metadata: 4 corner element offsets + 4 bilinear weights.
__device__ int4   g_off[NMETA];
__device__ float4 g_w[NMETA];

__global__ void roi_meta_kernel(const float* __restrict__ boxes) {
    const int idx = blockIdx.x * blockDim.x + threadIdx.x;
    if (idx >= NMETA) return;
    const int box = idx / NPOS;
    const int pos = idx - box * NPOS;
    const int b = box >> 9;
    const int py = pos / POOL_;
    const int px = pos - py * POOL_;

    const float4 bx = __ldg((const float4*)(boxes + (size_t)box * 4));
    const float x1 = bx.x, y1 = bx.y, x2 = bx.z, y2 = bx.w;

    const float ys = y1 * (H_ - 1) + (float)py * ((y2 - y1) * (H_ - 1) / (POOL_ - 1));
    const float xs = x1 * (W_ - 1) + (float)px * ((x2 - x1) * (W_ - 1) / (POOL_ - 1));

    const float yf = floorf(ys);
    const float xf = floorf(xs);
    const float fy = ys - yf;
    const float fx = xs - xf;

    int yt = (int)yf, xl = (int)xf;
    int yb = yt + 1,  xr = xl + 1;
    yt = min(max(yt, 0), H_ - 1);
    yb = min(max(yb, 0), H_ - 1);
    xl = min(max(xl, 0), W_ - 1);
    xr = min(max(xr, 0), W_ - 1);

    const bool valid = (ys >= 0.f) && (ys <= (float)(H_ - 1)) &&
                       (xs >= 0.f) && (xs <= (float)(W_ - 1));
    const float v = valid ? 1.f : 0.f;

    const float wtl = (1.f - fy) * (1.f - fx) * v;
    const float wtr = (1.f - fy) * fx * v;
    const float wbl = fy * (1.f - fx) * v;
    const float wbr = fy * fx * v;

    const int base = b * (H_ * W_ * C_);
    int4 o;
    o.x = base + (yt * W_ + xl) * C_;
    o.y = base + (yt * W_ + xr) * C_;
    o.z = base + (yb * W_ + xl) * C_;
    o.w = base + (yb * W_ + xr) * C_;

    g_off[idx] = o;
    g_w[idx]   = make_float4(wtl, wtr, wbl, wbr);
}

__global__ void __launch_bounds__(448) roi_gather_kernel(const float* __restrict__ fm,
                                                         float* __restrict__ out) {
    // block (64,7): 64 lanes x float4 = 256 channels; 7 pool positions per block
    const int pos = blockIdx.y * POOL_ + threadIdx.y;   // 0..48 exact
    const int box = blockIdx.x;                         // 0..4095
    const int idx = box * NPOS + pos;

    const int4   offs = g_off[idx];   // uniform across warp -> broadcast
    const float4 w    = g_w[idx];

    const int c = threadIdx.x * 4;

    const float4 tl = __ldg((const float4*)(fm + offs.x + c));
    const float4 tr = __ldg((const float4*)(fm + offs.y + c));
    const float4 bl = __ldg((const float4*)(fm + offs.z + c));
    const float4 br = __ldg((const float4*)(fm + offs.w + c));

    float4 o;
    o.x = fmaf(br.x, w.w, fmaf(bl.x, w.z, fmaf(tr.x, w.y, tl.x * w.x)));
    o.y = fmaf(br.y, w.w, fmaf(bl.y, w.z, fmaf(tr.y, w.y, tl.y * w.x)));
    o.z = fmaf(br.z, w.w, fmaf(bl.z, w.z, fmaf(tr.z, w.y, tl.z * w.x)));
    o.w = fmaf(br.w, w.w, fmaf(bl.w, w.z, fmaf(tr.w, w.y, tl.w * w.x)));

    *(float4*)(out + ((size_t)idx * C_ + c)) = o;
}

extern "C" void kernel_launch(void* const* d_in, const int* in_sizes, int n_in,
                              void* d_out, int out_size) {
    const float* fm    = (const float*)d_in[0];   // [8,64,64,256]
    const float* boxes = (const float*)d_in[1];   // [8,512,4]
    float* out = (float*)d_out;                   // [8,512,7,7,256]

    roi_meta_kernel<<<(NMETA + 255) / 256, 256>>>(boxes);

    dim3 block(64, POOL_);          // 448 threads
    dim3 grid(NBOX, POOL_);         // (4096, 7)
    roi_gather_kernel<<<grid, block>>>(fm, out);
}

// round 3
// speedup vs baseline: 1.2925x; 1.2925x over previous
#include <cuda_runtime.h>

#define B_ 8
#define H_ 64
#define W_ 64
#define C_ 256
#define N_ 512
#define POOL_ 7
#define NPOS (POOL_ * POOL_)   // 49
#define NBOX (B_ * N_)         // 4096

__global__ void __launch_bounds__(448) roi_align_fused(const float* __restrict__ fm,
                                                       const float* __restrict__ boxes,
                                                       float* __restrict__ out) {
    __shared__ int4   s_off[NPOS];
    __shared__ float4 s_w[NPOS];

    const int box = blockIdx.x;                         // 0..4095
    const int tid = threadIdx.y * 64 + threadIdx.x;

    if (tid < NPOS) {
        const int b  = box >> 9;
        const int py = tid / POOL_;
        const int px = tid - py * POOL_;

        const float4 bx = __ldg((const float4*)(boxes + (size_t)box * 4));
        const float x1 = bx.x, y1 = bx.y, x2 = bx.z, y2 = bx.w;

        const float ys = y1 * (H_ - 1) + (float)py * ((y2 - y1) * (H_ - 1) / (POOL_ - 1));
        const float xs = x1 * (W_ - 1) + (float)px * ((x2 - x1) * (W_ - 1) / (POOL_ - 1));

        const float yf = floorf(ys);
        const float xf = floorf(xs);
        const float fy = ys - yf;
        const float fx = xs - xf;

        int yt = (int)yf, xl = (int)xf;
        int yb = yt + 1,  xr = xl + 1;
        yt = min(max(yt, 0), H_ - 1);
        yb = min(max(yb, 0), H_ - 1);
        xl = min(max(xl, 0), W_ - 1);
        xr = min(max(xr, 0), W_ - 1);

        const bool valid = (ys >= 0.f) && (ys <= (float)(H_ - 1)) &&
                           (xs >= 0.f) && (xs <= (float)(W_ - 1));
        const float v = valid ? 1.f : 0.f;

        s_w[tid] = make_float4((1.f - fy) * (1.f - fx) * v,
                               (1.f - fy) * fx * v,
                               fy * (1.f - fx) * v,
                               fy * fx * v);

        const int base = b * (H_ * W_ * C_);
        s_off[tid] = make_int4(base + (yt * W_ + xl) * C_,
                               base + (yt * W_ + xr) * C_,
                               base + (yb * W_ + xl) * C_,
                               base + (yb * W_ + xr) * C_);
    }
    __syncthreads();

    const int c = threadIdx.x * 4;                      // channel offset
    float* obase = out + (size_t)box * NPOS * C_ + c;

    #pragma unroll
    for (int py = 0; py < POOL_; py++) {
        const int pos = py * POOL_ + threadIdx.y;       // uniform per warp -> broadcast

        const int4   offs = s_off[pos];
        const float4 w    = s_w[pos];

        const float4 tl = __ldg((const float4*)(fm + offs.x + c));
        const float4 tr = __ldg((const float4*)(fm + offs.y + c));
        const float4 bl = __ldg((const float4*)(fm + offs.z + c));
        const float4 br = __ldg((const float4*)(fm + offs.w + c));

        float4 o;
        o.x = fmaf(br.x, w.w, fmaf(bl.x, w.z, fmaf(tr.x, w.y, tl.x * w.x)));
        o.y = fmaf(br.y, w.w, fmaf(bl.y, w.z, fmaf(tr.y, w.y, tl.y * w.x)));
        o.z = fmaf(br.z, w.w, fmaf(bl.z, w.z, fmaf(tr.z, w.y, tl.z * w.x)));
        o.w = fmaf(br.w, w.w, fmaf(bl.w, w.z, fmaf(tr.w, w.y, tl.w * w.x)));

        *(float4*)(obase + (size_t)pos * C_) = o;
    }
}

extern "C" void kernel_launch(void* const* d_in, const int* in_sizes, int n_in,
                              void* d_out, int out_size) {
    const float* fm    = (const float*)d_in[0];   // [8,64,64,256]
    const float* boxes = (const float*)d_in[1];   // [8,512,4]
    float* out = (float*)d_out;                   // [8,512,7,7,256]

    dim3 block(64, POOL_);      // 448 threads
    roi_align_fused<<<NBOX, block>>>(fm, boxes, out);
}

// round 4
// speedup vs baseline: 1.4365x; 1.1115x over previous
#include <cuda_runtime.h>

#define B_ 8
#define H_ 64
#define W_ 64
#define C_ 256
#define N_ 512
#define POOL_ 7
#define NPOS (POOL_ * POOL_)   // 49
#define NBOX (B_ * N_)         // 4096

__global__ void __launch_bounds__(448, 4) roi_align_fused(const float* __restrict__ fm,
                                                          const float* __restrict__ boxes,
                                                          float* __restrict__ out) {
    __shared__ int4   s_off[NPOS];
    __shared__ float4 s_w[NPOS];

    const int box = blockIdx.x;                         // 0..4095
    const int tid = threadIdx.y * 64 + threadIdx.x;

    if (tid < NPOS) {
        const int b  = box >> 9;
        const int py = tid / POOL_;
        const int px = tid - py * POOL_;

        const float4 bx = __ldg((const float4*)(boxes + (size_t)box * 4));
        const float x1 = bx.x, y1 = bx.y, x2 = bx.z, y2 = bx.w;

        const float ys = y1 * (H_ - 1) + (float)py * ((y2 - y1) * (H_ - 1) / (POOL_ - 1));
        const float xs = x1 * (W_ - 1) + (float)px * ((x2 - x1) * (W_ - 1) / (POOL_ - 1));

        const float yf = floorf(ys);
        const float xf = floorf(xs);
        const float fy = ys - yf;
        const float fx = xs - xf;

        int yt = (int)yf, xl = (int)xf;
        int yb = yt + 1,  xr = xl + 1;
        yt = min(max(yt, 0), H_ - 1);
        yb = min(max(yb, 0), H_ - 1);
        xl = min(max(xl, 0), W_ - 1);
        xr = min(max(xr, 0), W_ - 1);

        const bool valid = (ys >= 0.f) && (ys <= (float)(H_ - 1)) &&
                           (xs >= 0.f) && (xs <= (float)(W_ - 1));
        const float v = valid ? 1.f : 0.f;

        s_w[tid] = make_float4((1.f - fy) * (1.f - fx) * v,
                               (1.f - fy) * fx * v,
                               fy * (1.f - fx) * v,
                               fy * fx * v);

        const int base = b * (H_ * W_ * C_);
        s_off[tid] = make_int4(base + (yt * W_ + xl) * C_,
                               base + (yt * W_ + xr) * C_,
                               base + (yb * W_ + xl) * C_,
                               base + (yb * W_ + xr) * C_);
    }
    __syncthreads();

    const int c = threadIdx.x * 4;                      // channel offset
    float* obase = out + (size_t)box * NPOS * C_ + c;

    #pragma unroll
    for (int py = 0; py < POOL_; py++) {
        const int pos = py * POOL_ + threadIdx.y;       // uniform per warp -> broadcast

        const int4   offs = s_off[pos];
        const float4 w    = s_w[pos];

        const float4 tl = __ldg((const float4*)(fm + offs.x + c));
        const float4 tr = __ldg((const float4*)(fm + offs.y + c));
        const float4 bl = __ldg((const float4*)(fm + offs.z + c));
        const float4 br = __ldg((const float4*)(fm + offs.w + c));

        float4 o;
        o.x = fmaf(br.x, w.w, fmaf(bl.x, w.z, fmaf(tr.x, w.y, tl.x * w.x)));
        o.y = fmaf(br.y, w.w, fmaf(bl.y, w.z, fmaf(tr.y, w.y, tl.y * w.x)));
        o.z = fmaf(br.z, w.w, fmaf(bl.z, w.z, fmaf(tr.z, w.y, tl.z * w.x)));
        o.w = fmaf(br.w, w.w, fmaf(bl.w, w.z, fmaf(tr.w, w.y, tl.w * w.x)));

        __stcs((float4*)(obase + (size_t)pos * C_), o);
    }
}

extern "C" void kernel_launch(void* const* d_in, const int* in_sizes, int n_in,
                              void* d_out, int out_size) {
    const float* fm    = (const float*)d_in[0];   // [8,64,64,256]
    const float* boxes = (const float*)d_in[1];   // [8,512,4]
    float* out = (float*)d_out;                   // [8,512,7,7,256]

    dim3 block(64, POOL_);      // 448 threads
    roi_align_fused<<<NBOX, block>>>(fm, boxes, out);
}